// round 7
// baseline (speedup 1.0000x reference)
#include <cuda_runtime.h>
#include <cuda_bf16.h>
#include <cstdint>

#define N_NODES 50000
#define N_EDGES 800000
#define IN_F    32
#define HF      128   // H*F
#define NH      4
#define FD      32
#define G3      96    // 3*F

// ---------------- scratch (device globals) ------------------------------------
__device__ __align__(16) float g_feat[N_NODES * HF];   // (N,128)
__device__ __align__(16) float g_el  [N_NODES * NH];
__device__ __align__(16) float g_er  [N_NODES * NH];
__device__ __align__(16) float g_x   [N_NODES * HF];   // normalized agg = GRU input
__device__ __align__(16) float g_ew  [N_EDGES * NH];   // per-edge exp weights, CSR order
__device__ int g_cnt [N_NODES];
__device__ int g_rowp[N_NODES + 1];
__device__ int g_csrc[N_EDGES];
__device__ int g_idx64;

__device__ __forceinline__ int ldidx(const void* p, int e, int is64) {
    return is64 ? (int)((const long long*)p)[e] : ((const int*)p)[e];
}
__device__ __forceinline__ float lrelu(float x) { return x > 0.f ? x : 0.2f * x; }

// ---- packed f32x2 helpers ----
typedef unsigned long long ull;
__device__ __forceinline__ ull pk(float lo, float hi) {
    ull r; asm("mov.b64 %0, {%1,%2};" : "=l"(r) : "f"(lo), "f"(hi)); return r;
}
__device__ __forceinline__ void fma2(ull& d, ull a, ull b) {
    asm("fma.rn.f32x2 %0, %1, %2, %0;" : "+l"(d) : "l"(a), "l"(b));
}
__device__ __forceinline__ float2 upk(ull v) {
    float2 f; asm("mov.b64 {%0,%1}, %2;" : "=f"(f.x), "=f"(f.y) : "l"(v)); return f;
}

// ---------------- K0: probe dtype + zero counters ------------------------------
__global__ void k_init(const unsigned* __restrict__ raw) {
    int i = blockIdx.x * blockDim.x + threadIdx.x;
    if (i < N_NODES) g_cnt[i] = 0;
    if (blockIdx.x == 0 && threadIdx.x == 0) {
        unsigned any = 0;
#pragma unroll
        for (int k = 1; k < 256; k += 2) any |= raw[k];
        g_idx64 = (any == 0u) ? 1 : 0;
    }
}

// ---------------- K1: fused feat-GEMM (+el/er) AND dst histogram ---------------
#define FEAT_BLOCKS 391   // ceil(50000/128)
__global__ void __launch_bounds__(256) k_feathist(
    const float* __restrict__ h, const float* __restrict__ Wg,
    const float* __restrict__ al, const float* __restrict__ ar,
    const void* __restrict__ dst)
{
    __shared__ float Ws[IN_F * HF];     // 16 KB
    __shared__ float hsm[128 * IN_F];   // 16 KB
    int t = threadIdx.x;
    if (blockIdx.x >= FEAT_BLOCKS) {
        // histogram part: 4 edges per thread, vectorized index loads
        int e4 = ((blockIdx.x - FEAT_BLOCKS) * 256 + t) * 4;
        if (e4 >= N_EDGES) return;
        int d0, d1, d2, d3;
        if (g_idx64) {
            longlong2 a = ((const longlong2*)dst)[e4 >> 1];
            longlong2 b = ((const longlong2*)dst)[(e4 >> 1) + 1];
            d0 = (int)a.x; d1 = (int)a.y; d2 = (int)b.x; d3 = (int)b.y;
        } else {
            int4 v = ((const int4*)dst)[e4 >> 2];
            d0 = v.x; d1 = v.y; d2 = v.z; d3 = v.w;
        }
        atomicAdd(&g_cnt[d0], 1); atomicAdd(&g_cnt[d1], 1);
        atomicAdd(&g_cnt[d2], 1); atomicAdd(&g_cnt[d3], 1);
        return;
    }
    // feat part: 128 nodes per block
    for (int i = t; i < IN_F * HF; i += 256) Ws[i] = Wg[i];
    int tc = t & 127, half = t >> 7;
    float a_l = al[tc], a_r = ar[tc];
    int nb = blockIdx.x * 128;
    for (int i = t; i < 128 * IN_F; i += 256) {
        int n = nb + (i >> 5);
        hsm[i] = (n < N_NODES) ? h[n * IN_F + (i & 31)] : 0.0f;
    }
    __syncthreads();
    int lane = t & 31, w = tc >> 5;
    int lbase = half * 64;
    for (int j = 0; j < 64; j++) {
        int n = nb + lbase + j;
        if (n >= N_NODES) break;
        float acc = 0.0f;
#pragma unroll
        for (int k = 0; k < IN_F; k++)
            acc = fmaf(hsm[(lbase + j) * IN_F + k], Ws[k * HF + tc], acc);
        g_feat[n * HF + tc] = acc;
        float pl = acc * a_l, pr = acc * a_r;
#pragma unroll
        for (int o = 16; o; o >>= 1) {
            pl += __shfl_down_sync(0xffffffffu, pl, o);
            pr += __shfl_down_sync(0xffffffffu, pr, o);
        }
        if (lane == 0) { g_el[n * NH + w] = pl; g_er[n * NH + w] = pr; }
    }
}

// ---------------- K2: single-block scan over 50k counts ------------------------
__global__ void __launch_bounds__(1024) k_scan() {
    const int C = (N_NODES + 1023) / 1024;   // 49
    int t = threadIdx.x, lane = t & 31, wid = t >> 5;
    int base = t * C;
    int s = 0;
    for (int i = 0; i < C; i++) {
        int idx = base + i;
        if (idx < N_NODES) s += g_cnt[idx];
    }
    int v = s;
#pragma unroll
    for (int o = 1; o < 32; o <<= 1) {
        int n = __shfl_up_sync(0xffffffffu, v, o);
        if (lane >= o) v += n;
    }
    __shared__ int wsum[32];
    if (lane == 31) wsum[wid] = v;
    __syncthreads();
    if (wid == 0) {
        int w = wsum[lane];
#pragma unroll
        for (int o = 1; o < 32; o <<= 1) {
            int n = __shfl_up_sync(0xffffffffu, w, o);
            if (lane >= o) w += n;
        }
        wsum[lane] = w;
    }
    __syncthreads();
    int run = v - s + (wid ? wsum[wid - 1] : 0);
    for (int i = 0; i < C; i++) {
        int idx = base + i;
        if (idx < N_NODES) {
            int c = g_cnt[idx];
            g_rowp[idx] = run;
            g_cnt[idx]  = run;
            run += c;
        }
    }
    if (t == 0) g_rowp[N_NODES] = N_EDGES;
}

// ---------------- K3: CSR fill + edge exp-weights ------------------------------
__global__ void __launch_bounds__(256) k_fill(
    const void* __restrict__ src, const void* __restrict__ dst)
{
    int e = blockIdx.x * blockDim.x + threadIdx.x;
    if (e >= N_EDGES) return;
    int is64 = g_idx64;
    int s = ldidx(src, e, is64);
    int d = ldidx(dst, e, is64);
    float4 a = *(const float4*)&g_el[s * NH];
    float4 b = *(const float4*)&g_er[d * NH];
    float4 w;
    w.x = __expf(lrelu(a.x + b.x));
    w.y = __expf(lrelu(a.y + b.y));
    w.z = __expf(lrelu(a.z + b.z));
    w.w = __expf(lrelu(a.w + b.w));
    int pos = atomicAdd(&g_cnt[d], 1);
    g_csrc[pos] = s;
    *(float4*)&g_ew[pos * NH] = w;
}

// ---------------- K4: aggregate (warp/node, feat gather only) ------------------
__global__ void __launch_bounds__(256) k_aggr() {
    int n = blockIdx.x * 8 + (threadIdx.x >> 5);
    if (n >= N_NODES) return;
    int lane = threadIdx.x & 31;
    int hd = lane >> 3;
    int col = lane * 4;
    int beg = g_rowp[n], end = g_rowp[n + 1];

    float4 acc = make_float4(0.f, 0.f, 0.f, 0.f);
    float dsum = 0.f;
    int j = beg;
    for (; j + 4 <= end; j += 4) {
        int s0 = g_csrc[j], s1 = g_csrc[j + 1], s2 = g_csrc[j + 2], s3 = g_csrc[j + 3];
        float e0 = g_ew[(j + 0) * NH + hd];
        float e1 = g_ew[(j + 1) * NH + hd];
        float e2 = g_ew[(j + 2) * NH + hd];
        float e3 = g_ew[(j + 3) * NH + hd];
        float4 f0 = *(const float4*)&g_feat[s0 * HF + col];
        float4 f1 = *(const float4*)&g_feat[s1 * HF + col];
        float4 f2 = *(const float4*)&g_feat[s2 * HF + col];
        float4 f3 = *(const float4*)&g_feat[s3 * HF + col];
        acc.x = fmaf(f0.x, e0, acc.x); acc.y = fmaf(f0.y, e0, acc.y);
        acc.z = fmaf(f0.z, e0, acc.z); acc.w = fmaf(f0.w, e0, acc.w);
        acc.x = fmaf(f1.x, e1, acc.x); acc.y = fmaf(f1.y, e1, acc.y);
        acc.z = fmaf(f1.z, e1, acc.z); acc.w = fmaf(f1.w, e1, acc.w);
        acc.x = fmaf(f2.x, e2, acc.x); acc.y = fmaf(f2.y, e2, acc.y);
        acc.z = fmaf(f2.z, e2, acc.z); acc.w = fmaf(f2.w, e2, acc.w);
        acc.x = fmaf(f3.x, e3, acc.x); acc.y = fmaf(f3.y, e3, acc.y);
        acc.z = fmaf(f3.z, e3, acc.z); acc.w = fmaf(f3.w, e3, acc.w);
        dsum += (e0 + e1) + (e2 + e3);
    }
    for (; j < end; j++) {
        int s = g_csrc[j];
        float ee = g_ew[j * NH + hd];
        float4 f = *(const float4*)&g_feat[s * HF + col];
        acc.x = fmaf(f.x, ee, acc.x); acc.y = fmaf(f.y, ee, acc.y);
        acc.z = fmaf(f.z, ee, acc.z); acc.w = fmaf(f.w, ee, acc.w);
        dsum += ee;
    }
    float inv = (dsum > 0.f) ? 1.0f / dsum : 0.0f;
    acc.x *= inv; acc.y *= inv; acc.z *= inv; acc.w *= inv;
    *(float4*)&g_x[n * HF + col] = acc;
}

// ---------------- K5: GRU cell + ELU (f32x2 packed node-pairs) -----------------
#define W_PAD   132
#define WH_PAD  36
#define NODES_B 128

__global__ void __launch_bounds__(512) k_gru(
    const float* __restrict__ h,
    const float* __restrict__ Wih, const float* __restrict__ Whh,
    const float* __restrict__ bih, const float* __restrict__ bhh,
    float* __restrict__ out)
{
    extern __shared__ float sm[];
    float* sWih = sm;                         // [96][132]
    float* sWhh = sWih + G3 * W_PAD;          // [96][36]
    float* sbi  = sWhh + G3 * WH_PAD;         // 96
    float* sbh  = sbi + G3;                   // 96
    float* xs   = sbh + G3;                   // [128][128]
    float* hs   = xs + NODES_B * HF;          // [128][32]

    int t = threadIdx.x;
    for (int i = t; i < G3 * HF; i += 512) sWih[(i >> 7) * W_PAD + (i & 127)] = Wih[i];
    for (int i = t; i < G3 * FD; i += 512) sWhh[(i >> 5) * WH_PAD + (i & 31)] = Whh[i];
    if (t < G3) { sbi[t] = bih[t]; sbh[t] = bhh[t]; }

    int base = blockIdx.x * NODES_B;
    float4 z4 = make_float4(0.f, 0.f, 0.f, 0.f);
    float4* xs4 = (float4*)xs;
    float4* hs4 = (float4*)hs;
    for (int i = t; i < NODES_B * HF / 4; i += 512) {
        int n = base + (i >> 5);
        xs4[i] = (n < N_NODES) ? ((const float4*)g_x)[n * 32 + (i & 31)] : z4;
    }
    for (int i = t; i < NODES_B * FD / 4; i += 512) {
        int n = base + (i >> 3);
        hs4[i] = (n < N_NODES) ? ((const float4*)h)[n * 8 + (i & 7)] : z4;
    }
    __syncthreads();

    int oi = t & 31, ni = t >> 5;   // 16 warps, 8 nodes each (4 pairs)
    ull accr[4], accz[4], accn[4], hccr[4], hccz[4], hccn[4];
    {
        float br = sbi[oi], bz = sbi[32 + oi], bn = sbi[64 + oi];
        float cr = sbh[oi], cz = sbh[32 + oi], cn = sbh[64 + oi];
#pragma unroll
        for (int p = 0; p < 4; p++) {
            accr[p] = pk(br, br); accz[p] = pk(bz, bz); accn[p] = pk(bn, bn);
            hccr[p] = pk(cr, cr); hccz[p] = pk(cz, cz); hccn[p] = pk(cn, cn);
        }
    }
    for (int k = 0; k < HF; k += 4) {
        float4 w0 = *(const float4*)&sWih[oi * W_PAD + k];
        float4 w1 = *(const float4*)&sWih[(32 + oi) * W_PAD + k];
        float4 w2 = *(const float4*)&sWih[(64 + oi) * W_PAD + k];
        ull w0x = pk(w0.x, w0.x), w0y = pk(w0.y, w0.y), w0z = pk(w0.z, w0.z), w0w = pk(w0.w, w0.w);
        ull w1x = pk(w1.x, w1.x), w1y = pk(w1.y, w1.y), w1z = pk(w1.z, w1.z), w1w = pk(w1.w, w1.w);
        ull w2x = pk(w2.x, w2.x), w2y = pk(w2.y, w2.y), w2z = pk(w2.z, w2.z), w2w = pk(w2.w, w2.w);
#pragma unroll
        for (int p = 0; p < 4; p++) {
            float4 xa = *(const float4*)&xs[(ni * 8 + 2 * p) * HF + k];
            float4 xb = *(const float4*)&xs[(ni * 8 + 2 * p + 1) * HF + k];
            ull x0 = pk(xa.x, xb.x), x1 = pk(xa.y, xb.y), x2 = pk(xa.z, xb.z), x3 = pk(xa.w, xb.w);
            fma2(accr[p], x0, w0x); fma2(accr[p], x1, w0y); fma2(accr[p], x2, w0z); fma2(accr[p], x3, w0w);
            fma2(accz[p], x0, w1x); fma2(accz[p], x1, w1y); fma2(accz[p], x2, w1z); fma2(accz[p], x3, w1w);
            fma2(accn[p], x0, w2x); fma2(accn[p], x1, w2y); fma2(accn[p], x2, w2z); fma2(accn[p], x3, w2w);
        }
    }
    for (int k = 0; k < FD; k += 4) {
        float4 w0 = *(const float4*)&sWhh[oi * WH_PAD + k];
        float4 w1 = *(const float4*)&sWhh[(32 + oi) * WH_PAD + k];
        float4 w2 = *(const float4*)&sWhh[(64 + oi) * WH_PAD + k];
        ull w0x = pk(w0.x, w0.x), w0y = pk(w0.y, w0.y), w0z = pk(w0.z, w0.z), w0w = pk(w0.w, w0.w);
        ull w1x = pk(w1.x, w1.x), w1y = pk(w1.y, w1.y), w1z = pk(w1.z, w1.z), w1w = pk(w1.w, w1.w);
        ull w2x = pk(w2.x, w2.x), w2y = pk(w2.y, w2.y), w2z = pk(w2.z, w2.z), w2w = pk(w2.w, w2.w);
#pragma unroll
        for (int p = 0; p < 4; p++) {
            float4 ha = *(const float4*)&hs[(ni * 8 + 2 * p) * FD + k];
            float4 hb = *(const float4*)&hs[(ni * 8 + 2 * p + 1) * FD + k];
            ull x0 = pk(ha.x, hb.x), x1 = pk(ha.y, hb.y), x2 = pk(ha.z, hb.z), x3 = pk(ha.w, hb.w);
            fma2(hccr[p], x0, w0x); fma2(hccr[p], x1, w0y); fma2(hccr[p], x2, w0z); fma2(hccr[p], x3, w0w);
            fma2(hccz[p], x0, w1x); fma2(hccz[p], x1, w1y); fma2(hccz[p], x2, w1z); fma2(hccz[p], x3, w1w);
            fma2(hccn[p], x0, w2x); fma2(hccn[p], x1, w2y); fma2(hccn[p], x2, w2z); fma2(hccn[p], x3, w2w);
        }
    }
#pragma unroll
    for (int p = 0; p < 4; p++) {
        float2 gr = upk(accr[p]), gz = upk(accz[p]), gn = upk(accn[p]);
        float2 hr = upk(hccr[p]), hz = upk(hccz[p]), hn = upk(hccn[p]);
#pragma unroll
        for (int q = 0; q < 2; q++) {
            int nl = ni * 8 + 2 * p + q;
            int n = base + nl;
            if (n >= N_NODES) continue;
            float gi_r = q ? gr.y : gr.x, gi_z = q ? gz.y : gz.x, gi_n = q ? gn.y : gn.x;
            float gh_r = q ? hr.y : hr.x, gh_z = q ? hz.y : hz.x, gh_n = q ? hn.y : hn.x;
            float r  = 1.0f / (1.0f + __expf(-(gi_r + gh_r)));
            float z  = 1.0f / (1.0f + __expf(-(gi_z + gh_z)));
            float nn = tanhf(gi_n + r * gh_n);
            float hv = hs[nl * FD + oi];
            float hnew = (1.0f - z) * nn + z * hv;
            out[n * FD + oi] = hnew > 0.0f ? hnew : (__expf(hnew) - 1.0f);
        }
    }
}

// ---------------- launch -------------------------------------------------------
extern "C" void kernel_launch(void* const* d_in, const int* in_sizes, int n_in,
                              void* d_out, int out_size)
{
    const float* h    = (const float*)d_in[0];
    const float* Wg   = (const float*)d_in[1];
    const float* al   = (const float*)d_in[2];
    const float* ar   = (const float*)d_in[3];
    const float* Wih  = (const float*)d_in[4];
    const float* Whh  = (const float*)d_in[5];
    const float* bih  = (const float*)d_in[6];
    const float* bhh  = (const float*)d_in[7];
    const void*  src  = d_in[8];
    const void*  dst  = d_in[9];
    float* out = (float*)d_out;

    static bool attr_set = false;
    size_t gru_smem = (size_t)(G3 * W_PAD + G3 * WH_PAD + 2 * G3 +
                               NODES_B * HF + NODES_B * FD) * sizeof(float);
    if (!attr_set) {
        cudaFuncSetAttribute(k_gru, cudaFuncAttributeMaxDynamicSharedMemorySize, (int)gru_smem);
        attr_set = true;
    }

    int hist_blocks = (N_EDGES + 1023) / 1024;
    k_init    <<<(N_NODES + 255) / 256, 256>>>((const unsigned*)dst);
    k_feathist<<<FEAT_BLOCKS + hist_blocks, 256>>>(h, Wg, al, ar, dst);
    k_scan    <<<1, 1024>>>();
    k_fill    <<<(N_EDGES + 255) / 256, 256>>>(src, dst);
    k_aggr    <<<(N_NODES + 7) / 8, 256>>>();
    k_gru     <<<(N_NODES + NODES_B - 1) / NODES_B, 512, gru_smem>>>(h, Wih, Whh, bih, bhh, out);
}

// round 8
// speedup vs baseline: 1.0934x; 1.0934x over previous
#include <cuda_runtime.h>
#include <cuda_fp16.h>
#include <cstdint>

#define N_NODES 50000
#define N_EDGES 800000
#define IN_F    32
#define HF      128   // H*F
#define NH      4
#define FD      32
#define G3      96    // 3*F

// ---------------- scratch (device globals) ------------------------------------
__device__ __align__(16) __half g_feat[N_NODES * HF];  // (N,128) fp16 — gather stream
__device__ __align__(16) float g_el  [N_NODES * NH];
__device__ __align__(16) float g_er  [N_NODES * NH];
__device__ __align__(16) float g_x   [N_NODES * HF];   // normalized agg = GRU input
__device__ int g_cnt [N_NODES];
__device__ int g_rowp[N_NODES + 1];
__device__ int g_csrc[N_EDGES];
__device__ int g_idx64;

__device__ __forceinline__ int ldidx(const void* p, int e, int is64) {
    return is64 ? (int)((const long long*)p)[e] : ((const int*)p)[e];
}
__device__ __forceinline__ float lrelu(float x) { return x > 0.f ? x : 0.2f * x; }

// ---------------- K0: probe dtype + zero counters ------------------------------
__global__ void k_init(const unsigned* __restrict__ raw) {
    int i = blockIdx.x * blockDim.x + threadIdx.x;
    if (i < N_NODES) g_cnt[i] = 0;
    if (blockIdx.x == 0 && threadIdx.x == 0) {
        unsigned any = 0;
#pragma unroll
        for (int k = 1; k < 256; k += 2) any |= raw[k];
        g_idx64 = (any == 0u) ? 1 : 0;
    }
}

// ---------------- K1: fused feat-GEMM (+el/er) AND dst histogram ---------------
#define FEAT_BLOCKS 391   // ceil(50000/128)
__global__ void __launch_bounds__(256) k_feathist(
    const float* __restrict__ h, const float* __restrict__ Wg,
    const float* __restrict__ al, const float* __restrict__ ar,
    const void* __restrict__ dst)
{
    __shared__ float Ws[IN_F * HF];     // 16 KB
    __shared__ float hsm[128 * IN_F];   // 16 KB
    int t = threadIdx.x;
    if (blockIdx.x >= FEAT_BLOCKS) {
        // histogram: 4 edges per thread, vectorized index loads
        int e4 = ((blockIdx.x - FEAT_BLOCKS) * 256 + t) * 4;
        if (e4 >= N_EDGES) return;
        int d0, d1, d2, d3;
        if (g_idx64) {
            longlong2 a = ((const longlong2*)dst)[e4 >> 1];
            longlong2 b = ((const longlong2*)dst)[(e4 >> 1) + 1];
            d0 = (int)a.x; d1 = (int)a.y; d2 = (int)b.x; d3 = (int)b.y;
        } else {
            int4 v = ((const int4*)dst)[e4 >> 2];
            d0 = v.x; d1 = v.y; d2 = v.z; d3 = v.w;
        }
        atomicAdd(&g_cnt[d0], 1); atomicAdd(&g_cnt[d1], 1);
        atomicAdd(&g_cnt[d2], 1); atomicAdd(&g_cnt[d3], 1);
        return;
    }
    // feat part: 128 nodes per block
    for (int i = t; i < IN_F * HF; i += 256) Ws[i] = Wg[i];
    int tc = t & 127, half = t >> 7;
    float a_l = al[tc], a_r = ar[tc];
    int nb = blockIdx.x * 128;
    for (int i = t; i < 128 * IN_F; i += 256) {
        int n = nb + (i >> 5);
        hsm[i] = (n < N_NODES) ? h[n * IN_F + (i & 31)] : 0.0f;
    }
    __syncthreads();
    int lane = t & 31, w = tc >> 5;
    int lbase = half * 64;
    for (int j = 0; j < 64; j++) {
        int n = nb + lbase + j;
        if (n >= N_NODES) break;
        float acc = 0.0f;
#pragma unroll
        for (int k = 0; k < IN_F; k++)
            acc = fmaf(hsm[(lbase + j) * IN_F + k], Ws[k * HF + tc], acc);
        g_feat[n * HF + tc] = __float2half(acc);
        float pl = acc * a_l, pr = acc * a_r;
#pragma unroll
        for (int o = 16; o; o >>= 1) {
            pl += __shfl_down_sync(0xffffffffu, pl, o);
            pr += __shfl_down_sync(0xffffffffu, pr, o);
        }
        if (lane == 0) { g_el[n * NH + w] = pl; g_er[n * NH + w] = pr; }
    }
}

// ---------------- K2: single-block scan over 50k counts ------------------------
__global__ void __launch_bounds__(1024) k_scan() {
    const int C = (N_NODES + 1023) / 1024;   // 49
    int t = threadIdx.x, lane = t & 31, wid = t >> 5;
    int base = t * C;
    int s = 0;
    for (int i = 0; i < C; i++) {
        int idx = base + i;
        if (idx < N_NODES) s += g_cnt[idx];
    }
    int v = s;
#pragma unroll
    for (int o = 1; o < 32; o <<= 1) {
        int n = __shfl_up_sync(0xffffffffu, v, o);
        if (lane >= o) v += n;
    }
    __shared__ int wsum[32];
    if (lane == 31) wsum[wid] = v;
    __syncthreads();
    if (wid == 0) {
        int w = wsum[lane];
#pragma unroll
        for (int o = 1; o < 32; o <<= 1) {
            int n = __shfl_up_sync(0xffffffffu, w, o);
            if (lane >= o) w += n;
        }
        wsum[lane] = w;
    }
    __syncthreads();
    int run = v - s + (wid ? wsum[wid - 1] : 0);
    for (int i = 0; i < C; i++) {
        int idx = base + i;
        if (idx < N_NODES) {
            int c = g_cnt[idx];
            g_rowp[idx] = run;
            g_cnt[idx]  = run;
            run += c;
        }
    }
    if (t == 0) g_rowp[N_NODES] = N_EDGES;
}

// ---------------- K3: CSR fill -------------------------------------------------
__global__ void __launch_bounds__(256) k_fill(
    const void* __restrict__ src, const void* __restrict__ dst)
{
    int e = blockIdx.x * blockDim.x + threadIdx.x;
    if (e >= N_EDGES) return;
    int is64 = g_idx64;
    int d = ldidx(dst, e, is64);
    int pos = atomicAdd(&g_cnt[d], 1);
    g_csrc[pos] = ldidx(src, e, is64);
}

// ---------------- K4: single-pass softmax aggregate (warp/node, fp16 gather) ---
__global__ void __launch_bounds__(256) k_aggr() {
    int n = blockIdx.x * 8 + (threadIdx.x >> 5);
    if (n >= N_NODES) return;
    int lane = threadIdx.x & 31;
    int hd = lane >> 3;
    int col = lane * 4;
    int beg = g_rowp[n], end = g_rowp[n + 1];
    float er_h = g_er[n * NH + hd];

    float4 acc = make_float4(0.f, 0.f, 0.f, 0.f);
    float dsum = 0.f;
    int j = beg;
    for (; j + 4 <= end; j += 4) {
        int s0 = g_csrc[j], s1 = g_csrc[j + 1], s2 = g_csrc[j + 2], s3 = g_csrc[j + 3];
        float l0 = g_el[s0 * NH + hd];
        float l1 = g_el[s1 * NH + hd];
        float l2 = g_el[s2 * NH + hd];
        float l3 = g_el[s3 * NH + hd];
        __half2 a0 = *(const __half2*)&g_feat[s0 * HF + col];
        __half2 b0 = *(const __half2*)&g_feat[s0 * HF + col + 2];
        __half2 a1 = *(const __half2*)&g_feat[s1 * HF + col];
        __half2 b1 = *(const __half2*)&g_feat[s1 * HF + col + 2];
        __half2 a2 = *(const __half2*)&g_feat[s2 * HF + col];
        __half2 b2 = *(const __half2*)&g_feat[s2 * HF + col + 2];
        __half2 a3 = *(const __half2*)&g_feat[s3 * HF + col];
        __half2 b3 = *(const __half2*)&g_feat[s3 * HF + col + 2];
        float e0 = __expf(lrelu(l0 + er_h));
        float e1 = __expf(lrelu(l1 + er_h));
        float e2 = __expf(lrelu(l2 + er_h));
        float e3 = __expf(lrelu(l3 + er_h));
        float2 fa, fb;
        fa = __half22float2(a0); fb = __half22float2(b0);
        acc.x = fmaf(fa.x, e0, acc.x); acc.y = fmaf(fa.y, e0, acc.y);
        acc.z = fmaf(fb.x, e0, acc.z); acc.w = fmaf(fb.y, e0, acc.w);
        fa = __half22float2(a1); fb = __half22float2(b1);
        acc.x = fmaf(fa.x, e1, acc.x); acc.y = fmaf(fa.y, e1, acc.y);
        acc.z = fmaf(fb.x, e1, acc.z); acc.w = fmaf(fb.y, e1, acc.w);
        fa = __half22float2(a2); fb = __half22float2(b2);
        acc.x = fmaf(fa.x, e2, acc.x); acc.y = fmaf(fa.y, e2, acc.y);
        acc.z = fmaf(fb.x, e2, acc.z); acc.w = fmaf(fb.y, e2, acc.w);
        fa = __half22float2(a3); fb = __half22float2(b3);
        acc.x = fmaf(fa.x, e3, acc.x); acc.y = fmaf(fa.y, e3, acc.y);
        acc.z = fmaf(fb.x, e3, acc.z); acc.w = fmaf(fb.y, e3, acc.w);
        dsum += (e0 + e1) + (e2 + e3);
    }
    for (; j < end; j++) {
        int s = g_csrc[j];
        float ee = __expf(lrelu(g_el[s * NH + hd] + er_h));
        __half2 a = *(const __half2*)&g_feat[s * HF + col];
        __half2 b = *(const __half2*)&g_feat[s * HF + col + 2];
        float2 fa = __half22float2(a), fb = __half22float2(b);
        acc.x = fmaf(fa.x, ee, acc.x); acc.y = fmaf(fa.y, ee, acc.y);
        acc.z = fmaf(fb.x, ee, acc.z); acc.w = fmaf(fb.y, ee, acc.w);
        dsum += ee;
    }
    float inv = (dsum > 0.f) ? 1.0f / dsum : 0.0f;
    acc.x *= inv; acc.y *= inv; acc.z *= inv; acc.w *= inv;
    *(float4*)&g_x[n * HF + col] = acc;
}

// ---------------- K5: GRU cell + ELU (128 nodes/block, 8 nodes/thread) ---------
#define W_PAD   132
#define WH_PAD  36
#define NODES_B 128

__global__ void __launch_bounds__(512) k_gru(
    const float* __restrict__ h,
    const float* __restrict__ Wih, const float* __restrict__ Whh,
    const float* __restrict__ bih, const float* __restrict__ bhh,
    float* __restrict__ out)
{
    extern __shared__ float sm[];
    float* sWih = sm;                         // [96][132]
    float* sWhh = sWih + G3 * W_PAD;          // [96][36]
    float* sbi  = sWhh + G3 * WH_PAD;         // 96
    float* sbh  = sbi + G3;                   // 96
    float* xs   = sbh + G3;                   // [128][128]
    float* hs   = xs + NODES_B * HF;          // [128][32]

    int t = threadIdx.x;
    for (int i = t; i < G3 * HF; i += 512) sWih[(i >> 7) * W_PAD + (i & 127)] = Wih[i];
    for (int i = t; i < G3 * FD; i += 512) sWhh[(i >> 5) * WH_PAD + (i & 31)] = Whh[i];
    if (t < G3) { sbi[t] = bih[t]; sbh[t] = bhh[t]; }

    int base = blockIdx.x * NODES_B;
    float4 z4 = make_float4(0.f, 0.f, 0.f, 0.f);
    float4* xs4 = (float4*)xs;
    float4* hs4 = (float4*)hs;
    for (int i = t; i < NODES_B * HF / 4; i += 512) {
        int n = base + (i >> 5);
        xs4[i] = (n < N_NODES) ? ((const float4*)g_x)[n * 32 + (i & 31)] : z4;
    }
    for (int i = t; i < NODES_B * FD / 4; i += 512) {
        int n = base + (i >> 3);
        hs4[i] = (n < N_NODES) ? ((const float4*)h)[n * 8 + (i & 7)] : z4;
    }
    __syncthreads();

    int oi = t & 31, ni = t >> 5;   // 16 warps, 8 nodes each
    float gr[8], gz[8], gn[8], hr[8], hz[8], hn[8];
#pragma unroll
    for (int j = 0; j < 8; j++) {
        gr[j] = sbi[oi]; gz[j] = sbi[32 + oi]; gn[j] = sbi[64 + oi];
        hr[j] = sbh[oi]; hz[j] = sbh[32 + oi]; hn[j] = sbh[64 + oi];
    }
    for (int k = 0; k < HF; k += 4) {
        float4 w0 = *(const float4*)&sWih[oi * W_PAD + k];
        float4 w1 = *(const float4*)&sWih[(32 + oi) * W_PAD + k];
        float4 w2 = *(const float4*)&sWih[(64 + oi) * W_PAD + k];
#pragma unroll
        for (int j = 0; j < 8; j++) {
            float4 xv = *(const float4*)&xs[(ni * 8 + j) * HF + k];
            gr[j] = fmaf(w0.x, xv.x, fmaf(w0.y, xv.y, fmaf(w0.z, xv.z, fmaf(w0.w, xv.w, gr[j]))));
            gz[j] = fmaf(w1.x, xv.x, fmaf(w1.y, xv.y, fmaf(w1.z, xv.z, fmaf(w1.w, xv.w, gz[j]))));
            gn[j] = fmaf(w2.x, xv.x, fmaf(w2.y, xv.y, fmaf(w2.z, xv.z, fmaf(w2.w, xv.w, gn[j]))));
        }
    }
    for (int k = 0; k < FD; k += 4) {
        float4 w0 = *(const float4*)&sWhh[oi * WH_PAD + k];
        float4 w1 = *(const float4*)&sWhh[(32 + oi) * WH_PAD + k];
        float4 w2 = *(const float4*)&sWhh[(64 + oi) * WH_PAD + k];
#pragma unroll
        for (int j = 0; j < 8; j++) {
            float4 hv = *(const float4*)&hs[(ni * 8 + j) * FD + k];
            hr[j] = fmaf(w0.x, hv.x, fmaf(w0.y, hv.y, fmaf(w0.z, hv.z, fmaf(w0.w, hv.w, hr[j]))));
            hz[j] = fmaf(w1.x, hv.x, fmaf(w1.y, hv.y, fmaf(w1.z, hv.z, fmaf(w1.w, hv.w, hz[j]))));
            hn[j] = fmaf(w2.x, hv.x, fmaf(w2.y, hv.y, fmaf(w2.z, hv.z, fmaf(w2.w, hv.w, hn[j]))));
        }
    }
#pragma unroll
    for (int j = 0; j < 8; j++) {
        int n = base + ni * 8 + j;
        if (n >= N_NODES) continue;
        float r  = 1.0f / (1.0f + __expf(-(gr[j] + hr[j])));
        float z  = 1.0f / (1.0f + __expf(-(gz[j] + hz[j])));
        float nn = tanhf(gn[j] + r * hn[j]);
        float hv = hs[(ni * 8 + j) * FD + oi];
        float hnew = (1.0f - z) * nn + z * hv;
        out[n * FD + oi] = hnew > 0.0f ? hnew : (__expf(hnew) - 1.0f);
    }
}

// ---------------- launch -------------------------------------------------------
extern "C" void kernel_launch(void* const* d_in, const int* in_sizes, int n_in,
                              void* d_out, int out_size)
{
    const float* h    = (const float*)d_in[0];
    const float* Wg   = (const float*)d_in[1];
    const float* al   = (const float*)d_in[2];
    const float* ar   = (const float*)d_in[3];
    const float* Wih  = (const float*)d_in[4];
    const float* Whh  = (const float*)d_in[5];
    const float* bih  = (const float*)d_in[6];
    const float* bhh  = (const float*)d_in[7];
    const void*  src  = d_in[8];
    const void*  dst  = d_in[9];
    float* out = (float*)d_out;

    static bool attr_set = false;
    size_t gru_smem = (size_t)(G3 * W_PAD + G3 * WH_PAD + 2 * G3 +
                               NODES_B * HF + NODES_B * FD) * sizeof(float);
    if (!attr_set) {
        cudaFuncSetAttribute(k_gru, cudaFuncAttributeMaxDynamicSharedMemorySize, (int)gru_smem);
        attr_set = true;
    }

    int hist_blocks = (N_EDGES + 1023) / 1024;
    k_init    <<<(N_NODES + 255) / 256, 256>>>((const unsigned*)dst);
    k_feathist<<<FEAT_BLOCKS + hist_blocks, 256>>>(h, Wg, al, ar, dst);
    k_scan    <<<1, 1024>>>();
    k_fill    <<<(N_EDGES + 255) / 256, 256>>>(src, dst);
    k_aggr    <<<(N_NODES + 7) / 8, 256>>>();
    k_gru     <<<(N_NODES + NODES_B - 1) / NODES_B, 512, gru_smem>>>(h, Wih, Whh, bih, bhh, out);
}

// round 10
// speedup vs baseline: 1.1312x; 1.0345x over previous
#include <cuda_runtime.h>
#include <cuda_fp16.h>
#include <cstdint>

#define N_NODES 50000
#define N_EDGES 800000
#define IN_F    32
#define HF      128   // H*F
#define NH      4
#define FD      32
#define G3      96    // 3*F

// ---------------- scratch (device globals) ------------------------------------
__device__ __align__(16) __half g_feat[N_NODES * HF];  // (N,128) fp16 gather stream
__device__ __align__(16) float g_el  [N_NODES * NH];
__device__ __align__(16) float g_er  [N_NODES * NH];
__device__ __align__(16) float g_x   [N_NODES * HF];   // normalized agg = GRU input
__device__ __align__(16) float g_Wl  [IN_F * NH];      // W_gat head-projected by attn_l
__device__ __align__(16) float g_Wr  [IN_F * NH];
__device__ int g_cnt [N_NODES];
__device__ int g_rowp[N_NODES + 1];
__device__ int g_csrc[N_EDGES];
__device__ int g_idx64;

__device__ __forceinline__ int ldidx(const void* p, int e, int is64) {
    return is64 ? (int)((const long long*)p)[e] : ((const int*)p)[e];
}
__device__ __forceinline__ float lrelu(float x) { return x > 0.f ? x : 0.2f * x; }

// ---------------- K0: probe dtype + zero counters + project attn vecs ----------
__global__ void k_init(const unsigned* __restrict__ raw,
                       const float* __restrict__ Wg,
                       const float* __restrict__ al, const float* __restrict__ ar) {
    int i = blockIdx.x * blockDim.x + threadIdx.x;
    if (i < N_NODES) g_cnt[i] = 0;
    if (blockIdx.x == 0 && threadIdx.x == 0) {
        unsigned any = 0;
#pragma unroll
        for (int k = 1; k < 256; k += 2) any |= raw[k];
        g_idx64 = (any == 0u) ? 1 : 0;
    }
    if (blockIdx.x == 0 && threadIdx.x < IN_F * NH) {
        int k = threadIdx.x >> 2, hh = threadIdx.x & 3;
        float sl = 0.f, sr = 0.f;
#pragma unroll
        for (int f = 0; f < 32; f++) {
            float w = Wg[k * HF + hh * 32 + f];
            sl = fmaf(w, al[hh * 32 + f], sl);
            sr = fmaf(w, ar[hh * 32 + f], sr);
        }
        g_Wl[k * NH + hh] = sl;
        g_Wr[k * NH + hh] = sr;
    }
}

// ---------------- K1: fused feat-GEMM + el/er (projection) + dst histogram -----
#define FEAT_BLOCKS 391   // ceil(50000/128)
__global__ void __launch_bounds__(256) k_feathist(
    const float* __restrict__ h, const float* __restrict__ Wg,
    const void* __restrict__ dst)
{
    __shared__ float Ws[IN_F * HF];     // 16 KB
    __shared__ float hsm[128 * IN_F];   // 16 KB
    __shared__ float sWlr[IN_F * 8];    // [k][c]: c<4 -> Wl, c>=4 -> Wr
    int t = threadIdx.x;
    if (blockIdx.x >= FEAT_BLOCKS) {
        // histogram: 4 edges per thread, vectorized index loads
        int e4 = ((blockIdx.x - FEAT_BLOCKS) * 256 + t) * 4;
        if (e4 >= N_EDGES) return;
        int d0, d1, d2, d3;
        if (g_idx64) {
            longlong2 a = ((const longlong2*)dst)[e4 >> 1];
            longlong2 b = ((const longlong2*)dst)[(e4 >> 1) + 1];
            d0 = (int)a.x; d1 = (int)a.y; d2 = (int)b.x; d3 = (int)b.y;
        } else {
            int4 v = ((const int4*)dst)[e4 >> 2];
            d0 = v.x; d1 = v.y; d2 = v.z; d3 = v.w;
        }
        atomicAdd(&g_cnt[d0], 1); atomicAdd(&g_cnt[d1], 1);
        atomicAdd(&g_cnt[d2], 1); atomicAdd(&g_cnt[d3], 1);
        return;
    }
    // feat part: 128 nodes per block
    for (int i = t; i < IN_F * HF; i += 256) Ws[i] = Wg[i];
    if (t < IN_F * 8) {
        int k = t >> 3, c = t & 7;
        sWlr[t] = (c < 4) ? g_Wl[k * NH + c] : g_Wr[k * NH + (c - 4)];
    }
    int nb = blockIdx.x * 128;
    for (int i = t; i < 128 * IN_F; i += 256) {
        int n = nb + (i >> 5);
        hsm[i] = (n < N_NODES) ? h[n * IN_F + (i & 31)] : 0.0f;
    }
    __syncthreads();
    int tc = t & 127, half = t >> 7;
    int lbase = half * 64;
    for (int j = 0; j < 64; j++) {
        int n = nb + lbase + j;
        if (n >= N_NODES) break;
        float acc = 0.0f;
#pragma unroll
        for (int k = 0; k < IN_F; k++)
            acc = fmaf(hsm[(lbase + j) * IN_F + k], Ws[k * HF + tc], acc);
        g_feat[n * HF + tc] = __float2half(acc);
    }
    // el/er: 128 nodes x 8 outputs
    for (int i = t; i < 128 * 8; i += 256) {
        int j = i >> 3, c = i & 7;
        int n = nb + j;
        if (n >= N_NODES) continue;
        float s = 0.0f;
#pragma unroll
        for (int k = 0; k < IN_F; k++)
            s = fmaf(hsm[j * IN_F + k], sWlr[k * 8 + c], s);
        if (c < 4) g_el[n * NH + c] = s;
        else       g_er[n * NH + (c - 4)] = s;
    }
}

// ---------------- K2: single-block scan over 50k counts ------------------------
__global__ void __launch_bounds__(1024) k_scan() {
    const int C = (N_NODES + 1023) / 1024;   // 49
    int t = threadIdx.x, lane = t & 31, wid = t >> 5;
    int base = t * C;
    int s = 0;
    for (int i = 0; i < C; i++) {
        int idx = base + i;
        if (idx < N_NODES) s += g_cnt[idx];
    }
    int v = s;
#pragma unroll
    for (int o = 1; o < 32; o <<= 1) {
        int n = __shfl_up_sync(0xffffffffu, v, o);
        if (lane >= o) v += n;
    }
    __shared__ int wsum[32];
    if (lane == 31) wsum[wid] = v;
    __syncthreads();
    if (wid == 0) {
        int w = wsum[lane];
#pragma unroll
        for (int o = 1; o < 32; o <<= 1) {
            int n = __shfl_up_sync(0xffffffffu, w, o);
            if (lane >= o) w += n;
        }
        wsum[lane] = w;
    }
    __syncthreads();
    int run = v - s + (wid ? wsum[wid - 1] : 0);
    for (int i = 0; i < C; i++) {
        int idx = base + i;
        if (idx < N_NODES) {
            int c = g_cnt[idx];
            g_rowp[idx] = run;
            g_cnt[idx]  = run;
            run += c;
        }
    }
    if (t == 0) g_rowp[N_NODES] = N_EDGES;
}

// ---------------- K3: CSR fill -------------------------------------------------
__global__ void __launch_bounds__(256) k_fill(
    const void* __restrict__ src, const void* __restrict__ dst)
{
    int e = blockIdx.x * blockDim.x + threadIdx.x;
    if (e >= N_EDGES) return;
    int is64 = g_idx64;
    int d = ldidx(dst, e, is64);
    int pos = atomicAdd(&g_cnt[d], 1);
    g_csrc[pos] = ldidx(src, e, is64);
}

// ---------------- K4: aggregate (coalesced idx staging + shuffle bcast) --------
__global__ void __launch_bounds__(256) k_aggr() {
    int n = blockIdx.x * 8 + (threadIdx.x >> 5);
    if (n >= N_NODES) return;
    int lane = threadIdx.x & 31;
    int hd = lane >> 3, sub = lane & 7;
    int beg = g_rowp[n], end = g_rowp[n + 1];
    float er_h = g_er[n * NH + hd];

    float4 acc = make_float4(0.f, 0.f, 0.f, 0.f);
    float dsum = 0.f;
    int gbase = lane & 24;   // head-group base lane

    for (int base = beg; base < end; base += 32) {
        int cnt = min(32, end - base);
        // one coalesced load covers up to 32 edge indices (pad lanes -> 0, safe)
        int sidx = (lane < cnt) ? g_csrc[base + lane] : 0;
        for (int c0 = 0; c0 < cnt; c0 += 8) {
            // lane computes ee for edge (c0+sub) under head hd.
            // SHFL must be warp-uniform: execute unconditionally; padded lanes
            // source sidx=0 (valid address), then ee is masked to 0.
            int ej = c0 + sub;
            int sj_mine = __shfl_sync(0xffffffffu, sidx, ej);
            float ee_mine = (ej < cnt)
                ? __expf(lrelu(g_el[sj_mine * NH + hd] + er_h)) : 0.f;
            dsum += ee_mine;
            // distribute: 8 independent feat gathers
#pragma unroll
            for (int j = 0; j < 8; j++) {
                float ee = __shfl_sync(0xffffffffu, ee_mine, gbase + j);
                int sj   = __shfl_sync(0xffffffffu, sidx, c0 + j);
                uint2 fv = *(const uint2*)&g_feat[sj * HF + lane * 4];
                float2 fa = __half22float2(*(const __half2*)&fv.x);
                float2 fb = __half22float2(*(const __half2*)&fv.y);
                acc.x = fmaf(fa.x, ee, acc.x);
                acc.y = fmaf(fa.y, ee, acc.y);
                acc.z = fmaf(fb.x, ee, acc.z);
                acc.w = fmaf(fb.y, ee, acc.w);
            }
        }
    }
    // sum dsum within 8-lane head group
    dsum += __shfl_xor_sync(0xffffffffu, dsum, 1);
    dsum += __shfl_xor_sync(0xffffffffu, dsum, 2);
    dsum += __shfl_xor_sync(0xffffffffu, dsum, 4);
    float inv = (dsum > 0.f) ? 1.0f / dsum : 0.0f;
    acc.x *= inv; acc.y *= inv; acc.z *= inv; acc.w *= inv;
    *(float4*)&g_x[n * HF + lane * 4] = acc;
}

// ---------------- K5: GRU cell + ELU (128 nodes/block, 8 nodes/thread) ---------
#define W_PAD   132
#define WH_PAD  36
#define NODES_B 128

__global__ void __launch_bounds__(512) k_gru(
    const float* __restrict__ h,
    const float* __restrict__ Wih, const float* __restrict__ Whh,
    const float* __restrict__ bih, const float* __restrict__ bhh,
    float* __restrict__ out)
{
    extern __shared__ float sm[];
    float* sWih = sm;                         // [96][132]
    float* sWhh = sWih + G3 * W_PAD;          // [96][36]
    float* sbi  = sWhh + G3 * WH_PAD;         // 96
    float* sbh  = sbi + G3;                   // 96
    float* xs   = sbh + G3;                   // [128][128]
    float* hs   = xs + NODES_B * HF;          // [128][32]

    int t = threadIdx.x;
    for (int i = t; i < G3 * HF; i += 512) sWih[(i >> 7) * W_PAD + (i & 127)] = Wih[i];
    for (int i = t; i < G3 * FD; i += 512) sWhh[(i >> 5) * WH_PAD + (i & 31)] = Whh[i];
    if (t < G3) { sbi[t] = bih[t]; sbh[t] = bhh[t]; }

    int base = blockIdx.x * NODES_B;
    float4 z4 = make_float4(0.f, 0.f, 0.f, 0.f);
    float4* xs4 = (float4*)xs;
    float4* hs4 = (float4*)hs;
    for (int i = t; i < NODES_B * HF / 4; i += 512) {
        int n = base + (i >> 5);
        xs4[i] = (n < N_NODES) ? ((const float4*)g_x)[n * 32 + (i & 31)] : z4;
    }
    for (int i = t; i < NODES_B * FD / 4; i += 512) {
        int n = base + (i >> 3);
        hs4[i] = (n < N_NODES) ? ((const float4*)h)[n * 8 + (i & 7)] : z4;
    }
    __syncthreads();

    int oi = t & 31, ni = t >> 5;   // 16 warps, 8 nodes each
    float gr[8], gz[8], gn[8], hr[8], hz[8], hn[8];
#pragma unroll
    for (int j = 0; j < 8; j++) {
        gr[j] = sbi[oi]; gz[j] = sbi[32 + oi]; gn[j] = sbi[64 + oi];
        hr[j] = sbh[oi]; hz[j] = sbh[32 + oi]; hn[j] = sbh[64 + oi];
    }
    for (int k = 0; k < HF; k += 4) {
        float4 w0 = *(const float4*)&sWih[oi * W_PAD + k];
        float4 w1 = *(const float4*)&sWih[(32 + oi) * W_PAD + k];
        float4 w2 = *(const float4*)&sWih[(64 + oi) * W_PAD + k];
#pragma unroll
        for (int j = 0; j < 8; j++) {
            float4 xv = *(const float4*)&xs[(ni * 8 + j) * HF + k];
            gr[j] = fmaf(w0.x, xv.x, fmaf(w0.y, xv.y, fmaf(w0.z, xv.z, fmaf(w0.w, xv.w, gr[j]))));
            gz[j] = fmaf(w1.x, xv.x, fmaf(w1.y, xv.y, fmaf(w1.z, xv.z, fmaf(w1.w, xv.w, gz[j]))));
            gn[j] = fmaf(w2.x, xv.x, fmaf(w2.y, xv.y, fmaf(w2.z, xv.z, fmaf(w2.w, xv.w, gn[j]))));
        }
    }
    for (int k = 0; k < FD; k += 4) {
        float4 w0 = *(const float4*)&sWhh[oi * WH_PAD + k];
        float4 w1 = *(const float4*)&sWhh[(32 + oi) * WH_PAD + k];
        float4 w2 = *(const float4*)&sWhh[(64 + oi) * WH_PAD + k];
#pragma unroll
        for (int j = 0; j < 8; j++) {
            float4 hv = *(const float4*)&hs[(ni * 8 + j) * FD + k];
            hr[j] = fmaf(w0.x, hv.x, fmaf(w0.y, hv.y, fmaf(w0.z, hv.z, fmaf(w0.w, hv.w, hr[j]))));
            hz[j] = fmaf(w1.x, hv.x, fmaf(w1.y, hv.y, fmaf(w1.z, hv.z, fmaf(w1.w, hv.w, hz[j]))));
            hn[j] = fmaf(w2.x, hv.x, fmaf(w2.y, hv.y, fmaf(w2.z, hv.z, fmaf(w2.w, hv.w, hn[j]))));
        }
    }
#pragma unroll
    for (int j = 0; j < 8; j++) {
        int n = base + ni * 8 + j;
        if (n >= N_NODES) continue;
        float r  = 1.0f / (1.0f + __expf(-(gr[j] + hr[j])));
        float z  = 1.0f / (1.0f + __expf(-(gz[j] + hz[j])));
        float nn = tanhf(gn[j] + r * hn[j]);
        float hv = hs[(ni * 8 + j) * FD + oi];
        float hnew = (1.0f - z) * nn + z * hv;
        out[n * FD + oi] = hnew > 0.0f ? hnew : (__expf(hnew) - 1.0f);
    }
}

// ---------------- launch -------------------------------------------------------
extern "C" void kernel_launch(void* const* d_in, const int* in_sizes, int n_in,
                              void* d_out, int out_size)
{
    const float* h    = (const float*)d_in[0];
    const float* Wg   = (const float*)d_in[1];
    const float* al   = (const float*)d_in[2];
    const float* ar   = (const float*)d_in[3];
    const float* Wih  = (const float*)d_in[4];
    const float* Whh  = (const float*)d_in[5];
    const float* bih  = (const float*)d_in[6];
    const float* bhh  = (const float*)d_in[7];
    const void*  src  = d_in[8];
    const void*  dst  = d_in[9];
    float* out = (float*)d_out;

    static bool attr_set = false;
    size_t gru_smem = (size_t)(G3 * W_PAD + G3 * WH_PAD + 2 * G3 +
                               NODES_B * HF + NODES_B * FD) * sizeof(float);
    if (!attr_set) {
        cudaFuncSetAttribute(k_gru, cudaFuncAttributeMaxDynamicSharedMemorySize, (int)gru_smem);
        attr_set = true;
    }

    int hist_blocks = (N_EDGES + 1023) / 1024;
    k_init    <<<(N_NODES + 255) / 256, 256>>>((const unsigned*)dst, Wg, al, ar);
    k_feathist<<<FEAT_BLOCKS + hist_blocks, 256>>>(h, Wg, dst);
    k_scan    <<<1, 1024>>>();
    k_fill    <<<(N_EDGES + 255) / 256, 256>>>(src, dst);
    k_aggr    <<<(N_NODES + 7) / 8, 256>>>();
    k_gru     <<<(N_NODES + NODES_B - 1) / NODES_B, 512, gru_smem>>>(h, Wih, Whh, bih, bhh, out);
}

// round 11
// speedup vs baseline: 1.3211x; 1.1679x over previous
#include <cuda_runtime.h>
#include <cuda_fp16.h>
#include <cstdint>

#define N_NODES 50000
#define N_EDGES 800000
#define IN_F    32
#define HF      128   // H*F
#define NH      4
#define FD      32
#define G3      96    // 3*F

// ---------------- scratch (device globals) ------------------------------------
__device__ __align__(16) __half g_feat[N_NODES * HF];  // (N,128) fp16 gather stream
__device__ __align__(16) float g_el  [N_NODES * NH];
__device__ __align__(16) float g_er  [N_NODES * NH];
__device__ __align__(16) float g_x   [N_NODES * HF];   // normalized agg = GRU input
__device__ __align__(16) float g_Wl  [IN_F * NH];      // W_gat head-projected by attn_l
__device__ __align__(16) float g_Wr  [IN_F * NH];
__device__ int g_cnt [N_NODES];
__device__ int g_rowp[N_NODES + 1];
__device__ int g_csrc[N_EDGES];
__device__ int g_idx64;

__device__ __forceinline__ int ldidx(const void* p, int e, int is64) {
    return is64 ? (int)((const long long*)p)[e] : ((const int*)p)[e];
}
__device__ __forceinline__ float lrelu(float x) { return x > 0.f ? x : 0.2f * x; }

// ---------------- K0: probe dtype + zero counters + project attn vecs ----------
__global__ void k_init(const unsigned* __restrict__ raw,
                       const float* __restrict__ Wg,
                       const float* __restrict__ al, const float* __restrict__ ar) {
    int i = blockIdx.x * blockDim.x + threadIdx.x;
    if (i < N_NODES) g_cnt[i] = 0;
    if (blockIdx.x == 0 && threadIdx.x == 0) {
        unsigned any = 0;
#pragma unroll
        for (int k = 1; k < 256; k += 2) any |= raw[k];
        g_idx64 = (any == 0u) ? 1 : 0;
    }
    if (blockIdx.x == 0 && threadIdx.x < IN_F * NH) {
        int k = threadIdx.x >> 2, hh = threadIdx.x & 3;
        float sl = 0.f, sr = 0.f;
#pragma unroll
        for (int f = 0; f < 32; f++) {
            float w = Wg[k * HF + hh * 32 + f];
            sl = fmaf(w, al[hh * 32 + f], sl);
            sr = fmaf(w, ar[hh * 32 + f], sr);
        }
        g_Wl[k * NH + hh] = sl;
        g_Wr[k * NH + hh] = sr;
    }
}

// ---------------- K1: fused feat-GEMM + el/er (projection) + dst histogram -----
// feat threads register-cache their Ws column; h rows come as float4 LDS broadcasts.
#define FEAT_BLOCKS 391   // ceil(50000/128)
__global__ void __launch_bounds__(256) k_feathist(
    const float* __restrict__ h, const float* __restrict__ Wg,
    const void* __restrict__ dst)
{
    __shared__ float hsm[128 * IN_F];   // 16 KB
    __shared__ float sWlr[IN_F * 8];    // [k][c]: c<4 -> Wl, c>=4 -> Wr
    int t = threadIdx.x;
    if (blockIdx.x >= FEAT_BLOCKS) {
        // histogram: 4 edges per thread, vectorized index loads
        int e4 = ((blockIdx.x - FEAT_BLOCKS) * 256 + t) * 4;
        if (e4 >= N_EDGES) return;
        int d0, d1, d2, d3;
        if (g_idx64) {
            longlong2 a = ((const longlong2*)dst)[e4 >> 1];
            longlong2 b = ((const longlong2*)dst)[(e4 >> 1) + 1];
            d0 = (int)a.x; d1 = (int)a.y; d2 = (int)b.x; d3 = (int)b.y;
        } else {
            int4 v = ((const int4*)dst)[e4 >> 2];
            d0 = v.x; d1 = v.y; d2 = v.z; d3 = v.w;
        }
        atomicAdd(&g_cnt[d0], 1); atomicAdd(&g_cnt[d1], 1);
        atomicAdd(&g_cnt[d2], 1); atomicAdd(&g_cnt[d3], 1);
        return;
    }
    // feat part: 128 nodes per block; thread owns output column tc for 64 nodes
    int tc = t & 127, half = t >> 7;
    // register-cache W column tc (coalesced LDG: lanes tc consecutive)
    float wreg[IN_F];
#pragma unroll
    for (int k = 0; k < IN_F; k++) wreg[k] = Wg[k * HF + tc];
    if (t < IN_F * 8) {
        int k = t >> 3, c = t & 7;
        sWlr[t] = (c < 4) ? g_Wl[k * NH + c] : g_Wr[k * NH + (c - 4)];
    }
    int nb = blockIdx.x * 128;
    for (int i = t; i < 128 * IN_F; i += 256) {
        int n = nb + (i >> 5);
        hsm[i] = (n < N_NODES) ? h[n * IN_F + (i & 31)] : 0.0f;
    }
    __syncthreads();
    int lbase = half * 64;
    int jmax = min(64, N_NODES - nb - lbase);
    for (int j = 0; j < jmax; j++) {
        const float4* hrow = (const float4*)&hsm[(lbase + j) * IN_F];
        float a0 = 0.f, a1 = 0.f, a2 = 0.f, a3 = 0.f;
#pragma unroll
        for (int kk = 0; kk < IN_F / 4; kk++) {
            float4 hv = hrow[kk];                    // LDS.128 broadcast (16B)
            a0 = fmaf(hv.x, wreg[4 * kk + 0], a0);
            a1 = fmaf(hv.y, wreg[4 * kk + 1], a1);
            a2 = fmaf(hv.z, wreg[4 * kk + 2], a2);
            a3 = fmaf(hv.w, wreg[4 * kk + 3], a3);
        }
        g_feat[(nb + lbase + j) * HF + tc] = __float2half((a0 + a1) + (a2 + a3));
    }
    // el/er: 128 nodes x 8 outputs
    for (int i = t; i < 128 * 8; i += 256) {
        int j = i >> 3, c = i & 7;
        int n = nb + j;
        if (n >= N_NODES) continue;
        float s = 0.0f;
#pragma unroll
        for (int k = 0; k < IN_F; k++)
            s = fmaf(hsm[j * IN_F + k], sWlr[k * 8 + c], s);
        if (c < 4) g_el[n * NH + c] = s;
        else       g_er[n * NH + (c - 4)] = s;
    }
}

// ---------------- K2: single-block scan over 50k counts ------------------------
__global__ void __launch_bounds__(1024) k_scan() {
    const int C = (N_NODES + 1023) / 1024;   // 49
    int t = threadIdx.x, lane = t & 31, wid = t >> 5;
    int base = t * C;
    int s = 0;
    for (int i = 0; i < C; i++) {
        int idx = base + i;
        if (idx < N_NODES) s += g_cnt[idx];
    }
    int v = s;
#pragma unroll
    for (int o = 1; o < 32; o <<= 1) {
        int n = __shfl_up_sync(0xffffffffu, v, o);
        if (lane >= o) v += n;
    }
    __shared__ int wsum[32];
    if (lane == 31) wsum[wid] = v;
    __syncthreads();
    if (wid == 0) {
        int w = wsum[lane];
#pragma unroll
        for (int o = 1; o < 32; o <<= 1) {
            int n = __shfl_up_sync(0xffffffffu, w, o);
            if (lane >= o) w += n;
        }
        wsum[lane] = w;
    }
    __syncthreads();
    int run = v - s + (wid ? wsum[wid - 1] : 0);
    for (int i = 0; i < C; i++) {
        int idx = base + i;
        if (idx < N_NODES) {
            int c = g_cnt[idx];
            g_rowp[idx] = run;
            g_cnt[idx]  = run;
            run += c;
        }
    }
    if (t == 0) g_rowp[N_NODES] = N_EDGES;
}

// ---------------- K3: CSR fill -------------------------------------------------
__global__ void __launch_bounds__(256) k_fill(
    const void* __restrict__ src, const void* __restrict__ dst)
{
    int e = blockIdx.x * blockDim.x + threadIdx.x;
    if (e >= N_EDGES) return;
    int is64 = g_idx64;
    int d = ldidx(dst, e, is64);
    int pos = atomicAdd(&g_cnt[d], 1);
    g_csrc[pos] = ldidx(src, e, is64);
}

// ---------------- K4: aggregate (coalesced idx staging + shuffle bcast) --------
__global__ void __launch_bounds__(256) k_aggr() {
    int n = blockIdx.x * 8 + (threadIdx.x >> 5);
    if (n >= N_NODES) return;
    int lane = threadIdx.x & 31;
    int hd = lane >> 3, sub = lane & 7;
    int beg = g_rowp[n], end = g_rowp[n + 1];
    float er_h = g_er[n * NH + hd];

    float4 acc = make_float4(0.f, 0.f, 0.f, 0.f);
    float dsum = 0.f;
    int gbase = lane & 24;   // head-group base lane

    for (int base = beg; base < end; base += 32) {
        int cnt = min(32, end - base);
        int sidx = (lane < cnt) ? g_csrc[base + lane] : 0;
        for (int c0 = 0; c0 < cnt; c0 += 8) {
            int ej = c0 + sub;
            int sj_mine = __shfl_sync(0xffffffffu, sidx, ej);
            float ee_mine = (ej < cnt)
                ? __expf(lrelu(g_el[sj_mine * NH + hd] + er_h)) : 0.f;
            dsum += ee_mine;
#pragma unroll
            for (int j = 0; j < 8; j++) {
                float ee = __shfl_sync(0xffffffffu, ee_mine, gbase + j);
                int sj   = __shfl_sync(0xffffffffu, sidx, c0 + j);
                uint2 fv = *(const uint2*)&g_feat[sj * HF + lane * 4];
                float2 fa = __half22float2(*(const __half2*)&fv.x);
                float2 fb = __half22float2(*(const __half2*)&fv.y);
                acc.x = fmaf(fa.x, ee, acc.x);
                acc.y = fmaf(fa.y, ee, acc.y);
                acc.z = fmaf(fb.x, ee, acc.z);
                acc.w = fmaf(fb.y, ee, acc.w);
            }
        }
    }
    dsum += __shfl_xor_sync(0xffffffffu, dsum, 1);
    dsum += __shfl_xor_sync(0xffffffffu, dsum, 2);
    dsum += __shfl_xor_sync(0xffffffffu, dsum, 4);
    float inv = (dsum > 0.f) ? 1.0f / dsum : 0.0f;
    acc.x *= inv; acc.y *= inv; acc.z *= inv; acc.w *= inv;
    *(float4*)&g_x[n * HF + lane * 4] = acc;
}

// ---------------- K5: GRU cell + ELU (128 nodes/block, 8 nodes/thread) ---------
#define W_PAD   132
#define WH_PAD  36
#define NODES_B 128

__global__ void __launch_bounds__(512) k_gru(
    const float* __restrict__ h,
    const float* __restrict__ Wih, const float* __restrict__ Whh,
    const float* __restrict__ bih, const float* __restrict__ bhh,
    float* __restrict__ out)
{
    extern __shared__ float sm[];
    float* sWih = sm;                         // [96][132]
    float* sWhh = sWih + G3 * W_PAD;          // [96][36]
    float* sbi  = sWhh + G3 * WH_PAD;         // 96
    float* sbh  = sbi + G3;                   // 96
    float* xs   = sbh + G3;                   // [128][128]
    float* hs   = xs + NODES_B * HF;          // [128][32]

    int t = threadIdx.x;
    for (int i = t; i < G3 * HF; i += 512) sWih[(i >> 7) * W_PAD + (i & 127)] = Wih[i];
    for (int i = t; i < G3 * FD; i += 512) sWhh[(i >> 5) * WH_PAD + (i & 31)] = Whh[i];
    if (t < G3) { sbi[t] = bih[t]; sbh[t] = bhh[t]; }

    int base = blockIdx.x * NODES_B;
    float4 z4 = make_float4(0.f, 0.f, 0.f, 0.f);
    float4* xs4 = (float4*)xs;
    float4* hs4 = (float4*)hs;
    for (int i = t; i < NODES_B * HF / 4; i += 512) {
        int n = base + (i >> 5);
        xs4[i] = (n < N_NODES) ? ((const float4*)g_x)[n * 32 + (i & 31)] : z4;
    }
    for (int i = t; i < NODES_B * FD / 4; i += 512) {
        int n = base + (i >> 3);
        hs4[i] = (n < N_NODES) ? ((const float4*)h)[n * 8 + (i & 7)] : z4;
    }
    __syncthreads();

    int oi = t & 31, ni = t >> 5;   // 16 warps, 8 nodes each
    float gr[8], gz[8], gn[8], hr[8], hz[8], hn[8];
#pragma unroll
    for (int j = 0; j < 8; j++) {
        gr[j] = sbi[oi]; gz[j] = sbi[32 + oi]; gn[j] = sbi[64 + oi];
        hr[j] = sbh[oi]; hz[j] = sbh[32 + oi]; hn[j] = sbh[64 + oi];
    }
    for (int k = 0; k < HF; k += 4) {
        float4 w0 = *(const float4*)&sWih[oi * W_PAD + k];
        float4 w1 = *(const float4*)&sWih[(32 + oi) * W_PAD + k];
        float4 w2 = *(const float4*)&sWih[(64 + oi) * W_PAD + k];
#pragma unroll
        for (int j = 0; j < 8; j++) {
            float4 xv = *(const float4*)&xs[(ni * 8 + j) * HF + k];
            gr[j] = fmaf(w0.x, xv.x, fmaf(w0.y, xv.y, fmaf(w0.z, xv.z, fmaf(w0.w, xv.w, gr[j]))));
            gz[j] = fmaf(w1.x, xv.x, fmaf(w1.y, xv.y, fmaf(w1.z, xv.z, fmaf(w1.w, xv.w, gz[j]))));
            gn[j] = fmaf(w2.x, xv.x, fmaf(w2.y, xv.y, fmaf(w2.z, xv.z, fmaf(w2.w, xv.w, gn[j]))));
        }
    }
    for (int k = 0; k < FD; k += 4) {
        float4 w0 = *(const float4*)&sWhh[oi * WH_PAD + k];
        float4 w1 = *(const float4*)&sWhh[(32 + oi) * WH_PAD + k];
        float4 w2 = *(const float4*)&sWhh[(64 + oi) * WH_PAD + k];
#pragma unroll
        for (int j = 0; j < 8; j++) {
            float4 hv = *(const float4*)&hs[(ni * 8 + j) * FD + k];
            hr[j] = fmaf(w0.x, hv.x, fmaf(w0.y, hv.y, fmaf(w0.z, hv.z, fmaf(w0.w, hv.w, hr[j]))));
            hz[j] = fmaf(w1.x, hv.x, fmaf(w1.y, hv.y, fmaf(w1.z, hv.z, fmaf(w1.w, hv.w, hz[j]))));
            hn[j] = fmaf(w2.x, hv.x, fmaf(w2.y, hv.y, fmaf(w2.z, hv.z, fmaf(w2.w, hv.w, hn[j]))));
        }
    }
#pragma unroll
    for (int j = 0; j < 8; j++) {
        int n = base + ni * 8 + j;
        if (n >= N_NODES) continue;
        float r  = 1.0f / (1.0f + __expf(-(gr[j] + hr[j])));
        float z  = 1.0f / (1.0f + __expf(-(gz[j] + hz[j])));
        float nn = tanhf(gn[j] + r * hn[j]);
        float hv = hs[(ni * 8 + j) * FD + oi];
        float hnew = (1.0f - z) * nn + z * hv;
        out[n * FD + oi] = hnew > 0.0f ? hnew : (__expf(hnew) - 1.0f);
    }
}

// ---------------- launch -------------------------------------------------------
extern "C" void kernel_launch(void* const* d_in, const int* in_sizes, int n_in,
                              void* d_out, int out_size)
{
    const float* h    = (const float*)d_in[0];
    const float* Wg   = (const float*)d_in[1];
    const float* al   = (const float*)d_in[2];
    const float* ar   = (const float*)d_in[3];
    const float* Wih  = (const float*)d_in[4];
    const float* Whh  = (const float*)d_in[5];
    const float* bih  = (const float*)d_in[6];
    const float* bhh  = (const float*)d_in[7];
    const void*  src  = d_in[8];
    const void*  dst  = d_in[9];
    float* out = (float*)d_out;

    static bool attr_set = false;
    size_t gru_smem = (size_t)(G3 * W_PAD + G3 * WH_PAD + 2 * G3 +
                               NODES_B * HF + NODES_B * FD) * sizeof(float);
    if (!attr_set) {
        cudaFuncSetAttribute(k_gru, cudaFuncAttributeMaxDynamicSharedMemorySize, (int)gru_smem);
        attr_set = true;
    }

    int hist_blocks = (N_EDGES + 1023) / 1024;
    k_init    <<<(N_NODES + 255) / 256, 256>>>((const unsigned*)dst, Wg, al, ar);
    k_feathist<<<FEAT_BLOCKS + hist_blocks, 256>>>(h, Wg, dst);
    k_scan    <<<1, 1024>>>();
    k_fill    <<<(N_EDGES + 255) / 256, 256>>>(src, dst);
    k_aggr    <<<(N_NODES + 7) / 8, 256>>>();
    k_gru     <<<(N_NODES + NODES_B - 1) / NODES_B, 512, gru_smem>>>(h, Wih, Whh, bih, bhh, out);
}

// round 12
// speedup vs baseline: 1.5772x; 1.1939x over previous
#include <cuda_runtime.h>
#include <cuda_fp16.h>
#include <mma.h>
#include <cstdint>
using namespace nvcuda;

#define N_NODES 50000
#define N_EDGES 800000
#define IN_F    32
#define HF      128   // H*F
#define NH      4
#define FD      32
#define G3      96    // 3*F

// ---------------- scratch (device globals) ------------------------------------
__device__ __align__(16) __half g_feat [N_NODES * HF];  // fp16 gather stream
__device__ __align__(16) float  g_el   [N_NODES * NH];
__device__ __align__(16) float  g_er   [N_NODES * NH];
__device__ __align__(16) __half g_xh   [N_NODES * HF];  // GRU input, fp16
__device__ __align__(16) __half g_Wih16[G3 * HF];       // Wih pre-converted
__device__ __align__(16) float  g_Wl   [IN_F * NH];
__device__ __align__(16) float  g_Wr   [IN_F * NH];
__device__ int g_cnt [N_NODES];
__device__ int g_rowp[N_NODES + 1];
__device__ int g_csrc[N_EDGES];
__device__ int g_idx64;

__device__ __forceinline__ int ldidx(const void* p, int e, int is64) {
    return is64 ? (int)((const long long*)p)[e] : ((const int*)p)[e];
}
__device__ __forceinline__ float lrelu(float x) { return x > 0.f ? x : 0.2f * x; }

// ---------------- K0: probe + zero counters + project attn vecs + Wih->fp16 ----
__global__ void k_init(const unsigned* __restrict__ raw,
                       const float* __restrict__ Wg,
                       const float* __restrict__ al, const float* __restrict__ ar,
                       const float* __restrict__ Wih) {
    int i = blockIdx.x * blockDim.x + threadIdx.x;
    if (i < N_NODES) g_cnt[i] = 0;
    if (i < G3 * HF) g_Wih16[i] = __float2half(Wih[i]);
    if (blockIdx.x == 0 && threadIdx.x == 0) {
        unsigned any = 0;
#pragma unroll
        for (int k = 1; k < 256; k += 2) any |= raw[k];
        g_idx64 = (any == 0u) ? 1 : 0;
    }
    if (blockIdx.x == 0 && threadIdx.x < IN_F * NH) {
        int k = threadIdx.x >> 2, hh = threadIdx.x & 3;
        float sl = 0.f, sr = 0.f;
#pragma unroll
        for (int f = 0; f < 32; f++) {
            float w = Wg[k * HF + hh * 32 + f];
            sl = fmaf(w, al[hh * 32 + f], sl);
            sr = fmaf(w, ar[hh * 32 + f], sr);
        }
        g_Wl[k * NH + hh] = sl;
        g_Wr[k * NH + hh] = sr;
    }
}

// ---------------- K1: feat-GEMM (reg-cached W col) + el/er + dst histogram -----
#define FEAT_BLOCKS 391   // ceil(50000/128)
__global__ void __launch_bounds__(256) k_feathist(
    const float* __restrict__ h, const float* __restrict__ Wg,
    const void* __restrict__ dst)
{
    __shared__ float hsm[128 * IN_F];   // 16 KB
    __shared__ float sWlr[IN_F * 8];
    int t = threadIdx.x;
    if (blockIdx.x >= FEAT_BLOCKS) {
        int e4 = ((blockIdx.x - FEAT_BLOCKS) * 256 + t) * 4;
        if (e4 >= N_EDGES) return;
        int d0, d1, d2, d3;
        if (g_idx64) {
            longlong2 a = ((const longlong2*)dst)[e4 >> 1];
            longlong2 b = ((const longlong2*)dst)[(e4 >> 1) + 1];
            d0 = (int)a.x; d1 = (int)a.y; d2 = (int)b.x; d3 = (int)b.y;
        } else {
            int4 v = ((const int4*)dst)[e4 >> 2];
            d0 = v.x; d1 = v.y; d2 = v.z; d3 = v.w;
        }
        atomicAdd(&g_cnt[d0], 1); atomicAdd(&g_cnt[d1], 1);
        atomicAdd(&g_cnt[d2], 1); atomicAdd(&g_cnt[d3], 1);
        return;
    }
    int tc = t & 127, half = t >> 7;
    float wreg[IN_F];
#pragma unroll
    for (int k = 0; k < IN_F; k++) wreg[k] = Wg[k * HF + tc];
    if (t < IN_F * 8) {
        int k = t >> 3, c = t & 7;
        sWlr[t] = (c < 4) ? g_Wl[k * NH + c] : g_Wr[k * NH + (c - 4)];
    }
    int nb = blockIdx.x * 128;
    for (int i = t; i < 128 * IN_F; i += 256) {
        int n = nb + (i >> 5);
        hsm[i] = (n < N_NODES) ? h[n * IN_F + (i & 31)] : 0.0f;
    }
    __syncthreads();
    int lbase = half * 64;
    int jmax = min(64, N_NODES - nb - lbase);
    for (int j = 0; j < jmax; j++) {
        const float4* hrow = (const float4*)&hsm[(lbase + j) * IN_F];
        float a0 = 0.f, a1 = 0.f, a2 = 0.f, a3 = 0.f;
#pragma unroll
        for (int kk = 0; kk < IN_F / 4; kk++) {
            float4 hv = hrow[kk];
            a0 = fmaf(hv.x, wreg[4 * kk + 0], a0);
            a1 = fmaf(hv.y, wreg[4 * kk + 1], a1);
            a2 = fmaf(hv.z, wreg[4 * kk + 2], a2);
            a3 = fmaf(hv.w, wreg[4 * kk + 3], a3);
        }
        g_feat[(nb + lbase + j) * HF + tc] = __float2half((a0 + a1) + (a2 + a3));
    }
    for (int i = t; i < 128 * 8; i += 256) {
        int j = i >> 3, c = i & 7;
        int n = nb + j;
        if (n >= N_NODES) continue;
        float s = 0.0f;
#pragma unroll
        for (int k = 0; k < IN_F; k++)
            s = fmaf(hsm[j * IN_F + k], sWlr[k * 8 + c], s);
        if (c < 4) g_el[n * NH + c] = s;
        else       g_er[n * NH + (c - 4)] = s;
    }
}

// ---------------- K2: single-block scan over 50k counts ------------------------
__global__ void __launch_bounds__(1024) k_scan() {
    const int C = (N_NODES + 1023) / 1024;
    int t = threadIdx.x, lane = t & 31, wid = t >> 5;
    int base = t * C;
    int s = 0;
    for (int i = 0; i < C; i++) {
        int idx = base + i;
        if (idx < N_NODES) s += g_cnt[idx];
    }
    int v = s;
#pragma unroll
    for (int o = 1; o < 32; o <<= 1) {
        int n = __shfl_up_sync(0xffffffffu, v, o);
        if (lane >= o) v += n;
    }
    __shared__ int wsum[32];
    if (lane == 31) wsum[wid] = v;
    __syncthreads();
    if (wid == 0) {
        int w = wsum[lane];
#pragma unroll
        for (int o = 1; o < 32; o <<= 1) {
            int n = __shfl_up_sync(0xffffffffu, w, o);
            if (lane >= o) w += n;
        }
        wsum[lane] = w;
    }
    __syncthreads();
    int run = v - s + (wid ? wsum[wid - 1] : 0);
    for (int i = 0; i < C; i++) {
        int idx = base + i;
        if (idx < N_NODES) {
            int c = g_cnt[idx];
            g_rowp[idx] = run;
            g_cnt[idx]  = run;
            run += c;
        }
    }
    if (t == 0) g_rowp[N_NODES] = N_EDGES;
}

// ---------------- K3: CSR fill -------------------------------------------------
__global__ void __launch_bounds__(256) k_fill(
    const void* __restrict__ src, const void* __restrict__ dst)
{
    int e = blockIdx.x * blockDim.x + threadIdx.x;
    if (e >= N_EDGES) return;
    int is64 = g_idx64;
    int d = ldidx(dst, e, is64);
    int pos = atomicAdd(&g_cnt[d], 1);
    g_csrc[pos] = ldidx(src, e, is64);
}

// ---------------- K4: aggregate -> writes fp16 GRU input -----------------------
__global__ void __launch_bounds__(256) k_aggr() {
    int n = blockIdx.x * 8 + (threadIdx.x >> 5);
    if (n >= N_NODES) return;
    int lane = threadIdx.x & 31;
    int hd = lane >> 3, sub = lane & 7;
    int beg = g_rowp[n], end = g_rowp[n + 1];
    float er_h = g_er[n * NH + hd];

    float4 acc = make_float4(0.f, 0.f, 0.f, 0.f);
    float dsum = 0.f;
    int gbase = lane & 24;

    for (int base = beg; base < end; base += 32) {
        int cnt = min(32, end - base);
        int sidx = (lane < cnt) ? g_csrc[base + lane] : 0;
        for (int c0 = 0; c0 < cnt; c0 += 8) {
            int ej = c0 + sub;
            int sj_mine = __shfl_sync(0xffffffffu, sidx, ej);
            float ee_mine = (ej < cnt)
                ? __expf(lrelu(g_el[sj_mine * NH + hd] + er_h)) : 0.f;
            dsum += ee_mine;
#pragma unroll
            for (int j = 0; j < 8; j++) {
                float ee = __shfl_sync(0xffffffffu, ee_mine, gbase + j);
                int sj   = __shfl_sync(0xffffffffu, sidx, c0 + j);
                uint2 fv = *(const uint2*)&g_feat[sj * HF + lane * 4];
                float2 fa = __half22float2(*(const __half2*)&fv.x);
                float2 fb = __half22float2(*(const __half2*)&fv.y);
                acc.x = fmaf(fa.x, ee, acc.x);
                acc.y = fmaf(fa.y, ee, acc.y);
                acc.z = fmaf(fb.x, ee, acc.z);
                acc.w = fmaf(fb.y, ee, acc.w);
            }
        }
    }
    dsum += __shfl_xor_sync(0xffffffffu, dsum, 1);
    dsum += __shfl_xor_sync(0xffffffffu, dsum, 2);
    dsum += __shfl_xor_sync(0xffffffffu, dsum, 4);
    float inv = (dsum > 0.f) ? 1.0f / dsum : 0.0f;
    __half2 h0 = __floats2half2_rn(acc.x * inv, acc.y * inv);
    __half2 h1 = __floats2half2_rn(acc.z * inv, acc.w * inv);
    uint2 st; st.x = *(unsigned*)&h0; st.y = *(unsigned*)&h1;
    *(uint2*)&g_xh[n * HF + lane * 4] = st;
}

// ---------------- K5: GRU — wmma fp16 GEMM for gi + scalar Whh path ------------
#define NODES_B 128
#define XLD     136   // fp16 row stride (16B multiple)
#define GILD    104   // fp32 gi row stride
#define WH_PAD  36

__global__ void __launch_bounds__(512) k_gru(
    const float* __restrict__ h,
    const float* __restrict__ Whh,
    const float* __restrict__ bih, const float* __restrict__ bhh,
    float* __restrict__ out)
{
    extern __shared__ __align__(16) char smraw[];
    float*  sGi  = (float*)smraw;                       // [128][104]
    float*  sH   = sGi + NODES_B * GILD;                // [128][32]
    float*  sWhh = sH + NODES_B * FD;                   // [96][36]
    float*  sbi  = sWhh + G3 * WH_PAD;                  // 96
    float*  sbh  = sbi + G3;                            // 96
    __half* sX   = (__half*)(sbh + G3);                 // [128][136]
    __half* sW   = sX + NODES_B * XLD;                  // [96][136]

    int t = threadIdx.x;
    int base = blockIdx.x * NODES_B;

    // stage x (fp16) rows: 128 rows x 16 uint4
    for (int i = t; i < NODES_B * 16; i += 512) {
        int r = i >> 4, c = i & 15;
        int n = base + r;
        uint4 v = make_uint4(0u, 0u, 0u, 0u);
        if (n < N_NODES) v = ((const uint4*)&g_xh[n * HF])[c];
        *(uint4*)&sX[r * XLD + c * 8] = v;
    }
    // stage Wih fp16: 96 rows x 16 uint4
    for (int i = t; i < G3 * 16; i += 512) {
        int r = i >> 4, c = i & 15;
        *(uint4*)&sW[r * XLD + c * 8] = ((const uint4*)&g_Wih16[r * HF])[c];
    }
    for (int i = t; i < G3 * FD; i += 512) sWhh[(i >> 5) * WH_PAD + (i & 31)] = Whh[i];
    if (t < G3) { sbi[t] = bih[t]; sbh[t] = bhh[t]; }
    float4 z4 = make_float4(0.f, 0.f, 0.f, 0.f);
    for (int i = t; i < NODES_B * FD / 4; i += 512) {
        int n = base + (i >> 3);
        ((float4*)sH)[i] = (n < N_NODES) ? ((const float4*)h)[n * 8 + (i & 7)] : z4;
    }
    __syncthreads();

    // ---- wmma: 16 warps; warp = (row-tile mt, col-half) covers 3 of 6 col tiles
    {
        int wid = t >> 5;
        int mt = wid >> 1, chalf = wid & 1;
        int m0 = mt * 16;
        wmma::fragment<wmma::accumulator, 16, 16, 16, float> acc[3];
#pragma unroll
        for (int c = 0; c < 3; c++) wmma::fill_fragment(acc[c], 0.0f);
#pragma unroll
        for (int k0 = 0; k0 < HF; k0 += 16) {
            wmma::fragment<wmma::matrix_a, 16, 16, 16, __half, wmma::row_major> fa;
            wmma::load_matrix_sync(fa, sX + m0 * XLD + k0, XLD);
#pragma unroll
            for (int c = 0; c < 3; c++) {
                int n0 = (chalf * 3 + c) * 16;
                // B = Wih^T: element (k,n) lives at sW[n*XLD + k] -> col_major, ld=XLD
                wmma::fragment<wmma::matrix_b, 16, 16, 16, __half, wmma::col_major> fb;
                wmma::load_matrix_sync(fb, sW + n0 * XLD + k0, XLD);
                wmma::mma_sync(acc[c], fa, fb, acc[c]);
            }
        }
#pragma unroll
        for (int c = 0; c < 3; c++)
            wmma::store_matrix_sync(sGi + m0 * GILD + (chalf * 3 + c) * 16,
                                    acc[c], GILD, wmma::mem_row_major);
    }
    __syncthreads();

    // ---- epilogue: 16 warps, 8 nodes each; oi = lane
    int oi = t & 31, ni = t >> 5;
    float hr[8], hz[8], hn[8];
#pragma unroll
    for (int j = 0; j < 8; j++) {
        hr[j] = sbh[oi]; hz[j] = sbh[32 + oi]; hn[j] = sbh[64 + oi];
    }
    for (int k = 0; k < FD; k += 4) {
        float4 w0 = *(const float4*)&sWhh[oi * WH_PAD + k];
        float4 w1 = *(const float4*)&sWhh[(32 + oi) * WH_PAD + k];
        float4 w2 = *(const float4*)&sWhh[(64 + oi) * WH_PAD + k];
#pragma unroll
        for (int j = 0; j < 8; j++) {
            float4 hv = *(const float4*)&sH[(ni * 8 + j) * FD + k];
            hr[j] = fmaf(w0.x, hv.x, fmaf(w0.y, hv.y, fmaf(w0.z, hv.z, fmaf(w0.w, hv.w, hr[j]))));
            hz[j] = fmaf(w1.x, hv.x, fmaf(w1.y, hv.y, fmaf(w1.z, hv.z, fmaf(w1.w, hv.w, hz[j]))));
            hn[j] = fmaf(w2.x, hv.x, fmaf(w2.y, hv.y, fmaf(w2.z, hv.z, fmaf(w2.w, hv.w, hn[j]))));
        }
    }
#pragma unroll
    for (int j = 0; j < 8; j++) {
        int nl = ni * 8 + j;
        int n = base + nl;
        if (n >= N_NODES) continue;
        float gi_r = sGi[nl * GILD + oi]      + sbi[oi];
        float gi_z = sGi[nl * GILD + 32 + oi] + sbi[32 + oi];
        float gi_n = sGi[nl * GILD + 64 + oi] + sbi[64 + oi];
        float r  = 1.0f / (1.0f + __expf(-(gi_r + hr[j])));
        float z  = 1.0f / (1.0f + __expf(-(gi_z + hz[j])));
        float nn = tanhf(gi_n + r * hn[j]);
        float hv = sH[nl * FD + oi];
        float hnew = (1.0f - z) * nn + z * hv;
        out[n * FD + oi] = hnew > 0.0f ? hnew : (__expf(hnew) - 1.0f);
    }
}

// ---------------- launch -------------------------------------------------------
extern "C" void kernel_launch(void* const* d_in, const int* in_sizes, int n_in,
                              void* d_out, int out_size)
{
    const float* h    = (const float*)d_in[0];
    const float* Wg   = (const float*)d_in[1];
    const float* al   = (const float*)d_in[2];
    const float* ar   = (const float*)d_in[3];
    const float* Wih  = (const float*)d_in[4];
    const float* Whh  = (const float*)d_in[5];
    const float* bih  = (const float*)d_in[6];
    const float* bhh  = (const float*)d_in[7];
    const void*  src  = d_in[8];
    const void*  dst  = d_in[9];
    float* out = (float*)d_out;

    size_t gru_smem = (size_t)(NODES_B * GILD + NODES_B * FD + G3 * WH_PAD + 2 * G3) * 4
                    + (size_t)(NODES_B * XLD + G3 * XLD) * 2;
    static bool attr_set = false;
    if (!attr_set) {
        cudaFuncSetAttribute(k_gru, cudaFuncAttributeMaxDynamicSharedMemorySize, (int)gru_smem);
        attr_set = true;
    }

    int hist_blocks = (N_EDGES + 1023) / 1024;
    k_init    <<<(N_NODES + 255) / 256, 256>>>((const unsigned*)dst, Wg, al, ar, Wih);
    k_feathist<<<FEAT_BLOCKS + hist_blocks, 256>>>(h, Wg, dst);
    k_scan    <<<1, 1024>>>();
    k_fill    <<<(N_EDGES + 255) / 256, 256>>>(src, dst);
    k_aggr    <<<(N_NODES + 7) / 8, 256>>>();
    k_gru     <<<(N_NODES + NODES_B - 1) / NODES_B, 512, gru_smem>>>(h, Whh, bih, bhh, out);
}